// round 16
// baseline (speedup 1.0000x reference)
#include <cuda_runtime.h>
#include <cuda_bf16.h>

// Sinkhorn EMD, N=M=1024, D=3, eps=0.01, iters read from input (3000).
// Persistent kernel, 128 CTAs x 256 threads; warp w of CTA b owns row b*8+w.
//
// Barrier composed ONLY of individually-proven pieces:
//   publish:  plain STG of 8 row values per CTA
//   arrive:   __syncthreads; tid0: atom.acq_rel.gpu.add d_cnt   (R15: correct)
//             -- release cumulativity orders this CTA's stores to L2
//   release:  last arrival: st.release.gpu d_gen = m+1          (R15: correct)
//   wait:     tid0 volatile equality spin on d_gen              (R12: cheap)
//   readers:  f/g staged ONCE per CTA into SMEM via 256 x
//             ld.volatile.global.v4 (strong, L2-direct; R13: correct; 8x fewer
//             strong loads than R13 => no LTS hotspot), then all warps read
//             the SMEM copy. No membar, no IVALL, no acquire-poll.
//
// d_cnt/d_gen are monotone with per-launch base snapshot and equality spins
// => graph-replay safe with no reset handshake (proven pattern).
//
// Math in the exp2 domain scaled by S = log2(e)/eps (S*eps*ln2 == 1,
// S*eps*ln(1024) == 10):  S*f_row = -10 - m - log2(sum_j exp2(args_j - m)).

#define Nn      1024
#define NCTA    128
#define NTH     256
#define S_CONST 144.26950408889634074f   // log2(e)/eps, eps = 0.01
#define INV_S   0.0069314718055994531f   // eps*ln2 = 1/S

#define SMEM_BYTES ((8 * 1024 * 2 + 1024) * 4)   // sSC + sSCT + staging = 68 KB

__device__ __align__(16) float d_Sf[Nn];      // S * f
__device__ __align__(16) float d_Sg[Nn];      // S * g
__device__ __align__(16) float d_rowsum[Nn];
__device__ unsigned d_cnt = 0;                 // monotone arrival counter
__device__ unsigned d_gen = 0;                 // monotone release word

__device__ __forceinline__ float ex2f(float x) {
    float r;
    asm("ex2.approx.ftz.f32 %0, %1;" : "=f"(r) : "f"(x));
    return r;
}
__device__ __forceinline__ unsigned atom_add_acqrel(unsigned* p, unsigned v) {
    unsigned old;
    asm volatile("atom.acq_rel.gpu.global.add.u32 %0, [%1], %2;"
                 : "=r"(old) : "l"(p), "r"(v) : "memory");
    return old;
}
__device__ __forceinline__ void st_release(unsigned* p, unsigned v) {
    asm volatile("st.release.gpu.global.u32 [%0], %1;" :: "l"(p), "r"(v) : "memory");
}
// Strong (L2-direct) data loads; proven correct in R13.
__device__ __forceinline__ float4 ldvol_f4(const float4* p) {
    float4 v;
    asm volatile("ld.volatile.global.v4.f32 {%0,%1,%2,%3}, [%4];"
                 : "=f"(v.x), "=f"(v.y), "=f"(v.z), "=f"(v.w) : "l"(p) : "memory");
    return v;
}
__device__ __forceinline__ float ldvol_f(const float* p) {
    float v;
    asm volatile("ld.volatile.global.f32 %0, [%1];" : "=f"(v) : "l"(p) : "memory");
    return v;
}

// Grid barrier: acq_rel arrival + release + volatile equality spin.
__device__ __forceinline__ void grid_bar(unsigned m) {
    __syncthreads();                                    // CTA's publishes ordered
    if (threadIdx.x == 0) {
        const unsigned want = m + 1u;
        unsigned prev = atom_add_acqrel(&d_cnt, 1u);    // release-arrive
        if (prev == m * (unsigned)NCTA + (unsigned)(NCTA - 1))
            st_release(&d_gen, want);                   // release to all
        while (*(volatile unsigned*)&d_gen != want) { } // cheap volatile spin
    }
    __syncthreads();
}

// Stage a 1024-float global vector into SMEM with strong loads (one float4
// per thread), then CTA-sync.
__device__ __forceinline__ void stage(const float* __restrict__ src,
                                      float4* __restrict__ shg) {
    shg[threadIdx.x] = ldvol_f4(((const float4*)src) + threadIdx.x);
    __syncthreads();
}

// One Sinkhorn half-update; g comes from the SMEM staging buffer.
//   dout[row] = -10 - m - log2( sum_j exp2( shg[j] - sC[w][j] - m ) )
template <bool HASG>
__device__ __forceinline__ void half_pass(const float* __restrict__ sC,
                                          const float4* __restrict__ shg,
                                          float* __restrict__ dout,
                                          int w, int lane, int row) {
    const float4* c4 = (const float4*)(sC + (w << 10));
    float args[32];
    float m = -3.4e38f;
#pragma unroll
    for (int k = 0; k < 8; k++) {
        const int idx = (k << 5) + lane;
        const float4 c = c4[idx];                       // LDS.128, conflict-free
        const float4 g = HASG ? shg[idx]                // LDS.128, conflict-free
                              : make_float4(0.f, 0.f, 0.f, 0.f);
        const float a0 = g.x - c.x;
        const float a1 = g.y - c.y;
        const float a2 = g.z - c.z;
        const float a3 = g.w - c.w;
        args[4 * k + 0] = a0; args[4 * k + 1] = a1;
        args[4 * k + 2] = a2; args[4 * k + 3] = a3;
        m = fmaxf(m, fmaxf(fmaxf(a0, a1), fmaxf(a2, a3)));
    }
#pragma unroll
    for (int off = 16; off; off >>= 1)
        m = fmaxf(m, __shfl_xor_sync(0xffffffffu, m, off));
    float sum = 0.f;
#pragma unroll
    for (int k = 0; k < 32; k++) sum += ex2f(args[k] - m);
#pragma unroll
    for (int off = 16; off; off >>= 1)
        sum += __shfl_xor_sync(0xffffffffu, sum, off);
    if (lane == 0)
        dout[row] = -10.0f - m - __log2f(sum);   // plain store, released at arrival
}

__global__ void __launch_bounds__(NTH, 1)
emd_kernel(const float* __restrict__ tgt,    // [1024,3]
           const float* __restrict__ outp,   // [1024,3]
           const int*   __restrict__ iters_ptr,
           float*       __restrict__ out) {
    extern __shared__ __align__(16) float smem[];
    float*  sSC  = smem;                        // [8][1024]  S*C rows
    float*  sSCT = smem + 8 * 1024;             // [8][1024]  S*C^T rows
    float4* shg  = (float4*)(smem + 16 * 1024); // 1024-float staging
    __shared__ float red[NTH];
    __shared__ unsigned sh_base;

    const int tid  = threadIdx.x;
    const int w    = tid >> 5;
    const int lane = tid & 31;
    const int bid  = (int)blockIdx.x;
    const int row  = (bid << 3) + w;

    // Per-launch base snapshot of the monotone release word (proven pattern).
    if (tid == 0) sh_base = *(volatile unsigned*)&d_gen;

    // ---- Phase A (CTA-local): build SMEM cost slices from point clouds ----
    {
        const float tx = tgt[row * 3 + 0], ty = tgt[row * 3 + 1], tz = tgt[row * 3 + 2];
        for (int j = lane; j < Nn; j += 32) {
            const float dx = tx - outp[j * 3 + 0];
            const float dy = ty - outp[j * 3 + 1];
            const float dz = tz - outp[j * 3 + 2];
            sSC[(w << 10) + j] = S_CONST * (dx * dx + dy * dy + dz * dz);
        }
        const float ox = outp[row * 3 + 0], oy = outp[row * 3 + 1], oz = outp[row * 3 + 2];
        for (int i = lane; i < Nn; i += 32) {
            const float dx = tgt[i * 3 + 0] - ox;
            const float dy = tgt[i * 3 + 1] - oy;
            const float dz = tgt[i * 3 + 2] - oz;
            sSCT[(w << 10) + i] = S_CONST * (dx * dx + dy * dy + dz * dz);
        }
    }
    __syncthreads();
    const unsigned base = sh_base;

    // ---- Phase B: Sinkhorn iterations ----
    const int iters = iters_ptr ? iters_ptr[0] : 3000;
    unsigned k = 0;
    // iteration 0 f-update: g == 0 (no staging needed)
    half_pass<false>(sSC, (const float4*)0, d_Sf, w, lane, row);
    grid_bar(base + (k++));
    // iteration 0 g-update
    stage(d_Sf, shg);
    half_pass<true>(sSCT, shg, d_Sg, w, lane, row);
    grid_bar(base + (k++));
    for (int it = 1; it < iters; it++) {
        stage(d_Sg, shg);
        half_pass<true>(sSC, shg, d_Sf, w, lane, row);
        grid_bar(base + (k++));
        stage(d_Sf, shg);
        half_pass<true>(sSCT, shg, d_Sg, w, lane, row);
        grid_bar(base + (k++));
    }

    // ---- Phase C: rowsum_i = sum_j exp2(Sf_i + Sg_j - SC_ij) * SC_ij ----
    stage(d_Sg, shg);
    {
        const float sfr = ldvol_f(&d_Sf[row]);
        const float4* c4 = (const float4*)(sSC + (w << 10));
        float acc = 0.f;
#pragma unroll
        for (int kk = 0; kk < 8; kk++) {
            const int idx = (kk << 5) + lane;
            const float4 c = c4[idx];
            const float4 g = shg[idx];
            acc += ex2f(sfr + g.x - c.x) * c.x;
            acc += ex2f(sfr + g.y - c.y) * c.y;
            acc += ex2f(sfr + g.z - c.z) * c.z;
            acc += ex2f(sfr + g.w - c.w) * c.w;
        }
#pragma unroll
        for (int off = 16; off; off >>= 1)
            acc += __shfl_xor_sync(0xffffffffu, acc, off);
        if (lane == 0) d_rowsum[row] = acc;
    }
    grid_bar(base + (k++));

    // ---- Deterministic final reduction by CTA 0; scale by 1/S ----
    if (bid == 0) {
        float v = 0.f;
        for (int i = tid; i < Nn; i += NTH) v += ldvol_f(&d_rowsum[i]);
        red[tid] = v;
        __syncthreads();
        for (int s = NTH >> 1; s > 0; s >>= 1) {
            if (tid < s) red[tid] += red[tid + s];
            __syncthreads();
        }
        if (tid == 0) out[0] = red[0] * INV_S;
    }
    // d_cnt and d_gen are monotone with per-launch base snapshot and equality
    // spins => graph replays need no reset handshake.
}

extern "C" void kernel_launch(void* const* d_in, const int* in_sizes, int n_in,
                              void* d_out, int out_size) {
    const float* tgt  = (const float*)d_in[0];
    const float* outp = (const float*)d_in[1];
    const int*   itp  = (n_in >= 3) ? (const int*)d_in[2] : nullptr;
    (void)in_sizes; (void)out_size;
    cudaFuncSetAttribute(emd_kernel, cudaFuncAttributeMaxDynamicSharedMemorySize,
                         SMEM_BYTES);
    emd_kernel<<<NCTA, NTH, SMEM_BYTES>>>(tgt, outp, itp, (float*)d_out);
}